// round 10
// baseline (speedup 1.0000x reference)
#include <cuda_runtime.h>
#include <cuda_fp16.h>

#define NB 16
#define HH 512
#define WW 512
#define HQ 256
#define WQ 256
#define RAD 7

// Scratch (device globals; allocation in kernel_launch is forbidden)
__device__ __half g_yh[NB * HH * WW];        // horizontally filtered Y diff (fp16)
__device__ __half g_ch[2 * NB * HQ * WQ];    // horizontally filtered chroma (fp16)
__device__ double g_acc[2];                  // [0]=Y sumsq, [1]=U+V sumsq
__device__ unsigned int g_done;              // completion counter (self-resetting)

// ---------------------------------------------------------------------------
// k_diff_h: YUV420 diff channels + horizontal 15-tap box filter, fused.
// One warp = one Y row-pair = one chroma row. grid 512, block 256 (8 warps).
// Outputs stored as fp16 (halves DRAM write + k_v read traffic).
// ---------------------------------------------------------------------------
__global__ void __launch_bounds__(256)
k_diff_h(const float* __restrict__ in, const float* __restrict__ tg) {
    __shared__ float sP[8][WW + 16];    // per-warp prefix buffer
    __shared__ float sC[8][2 * WQ];     // per-warp raw chroma rows (U|V)

    const unsigned FULL = 0xFFFFFFFFu;
    int warp = threadIdx.x >> 5;
    int lane = threadIdx.x & 31;

    if (blockIdx.x == 0 && threadIdx.x < 2) g_acc[threadIdx.x] = 0.0;

    int gw = blockIdx.x * 8 + warp;     // 0..4095 row-pairs
    int n  = gw >> 8;                   // image
    int hq = gw & 255;                  // chroma row / y row-pair

    const long plane = (long)HH * WW;
    const long p4 = plane >> 2, w4 = WW >> 2;
    long base4 = ((long)n * 3 * plane + (long)(2 * hq) * WW) >> 2;

    const float4* i4 = (const float4*)in;
    const float4* t4 = (const float4*)tg;

    float* U = sC[warp];
    float* V = sC[warp] + WQ;
    float* P = sP[warp];

    float4 yd0[4], yd1[4];

    #pragma unroll
    for (int c = 0; c < 4; ++c) {
        long o = base4 + c * 32 + lane;
        float4 a, b, dr0, dg0, db0, dr1, dg1, db1;
        a = i4[o];            b = t4[o];
        dr0 = make_float4(a.x-b.x, a.y-b.y, a.z-b.z, a.w-b.w);
        a = i4[o + p4];       b = t4[o + p4];
        dg0 = make_float4(a.x-b.x, a.y-b.y, a.z-b.z, a.w-b.w);
        a = i4[o + 2*p4];     b = t4[o + 2*p4];
        db0 = make_float4(a.x-b.x, a.y-b.y, a.z-b.z, a.w-b.w);
        a = i4[o + w4];       b = t4[o + w4];
        dr1 = make_float4(a.x-b.x, a.y-b.y, a.z-b.z, a.w-b.w);
        a = i4[o + w4 + p4];  b = t4[o + w4 + p4];
        dg1 = make_float4(a.x-b.x, a.y-b.y, a.z-b.z, a.w-b.w);
        a = i4[o + w4 + 2*p4];b = t4[o + w4 + 2*p4];
        db1 = make_float4(a.x-b.x, a.y-b.y, a.z-b.z, a.w-b.w);

        yd0[c] = make_float4(0.299f*dr0.x + 0.587f*dg0.x + 0.114f*db0.x,
                             0.299f*dr0.y + 0.587f*dg0.y + 0.114f*db0.y,
                             0.299f*dr0.z + 0.587f*dg0.z + 0.114f*db0.z,
                             0.299f*dr0.w + 0.587f*dg0.w + 0.114f*db0.w);
        yd1[c] = make_float4(0.299f*dr1.x + 0.587f*dg1.x + 0.114f*db1.x,
                             0.299f*dr1.y + 0.587f*dg1.y + 0.114f*db1.y,
                             0.299f*dr1.z + 0.587f*dg1.z + 0.114f*db1.z,
                             0.299f*dr1.w + 0.587f*dg1.w + 0.114f*db1.w);

        float drA = dr0.x + dr0.y + dr1.x + dr1.y;
        float dgA = dg0.x + dg0.y + dg1.x + dg1.y;
        float dbA = db0.x + db0.y + db1.x + db1.y;
        float drB = dr0.z + dr0.w + dr1.z + dr1.w;
        float dgB = dg0.z + dg0.w + dg1.z + dg1.w;
        float dbB = db0.z + db0.w + db1.z + db1.w;

        *(float2*)(U + c*64 + 2*lane) =
            make_float2(0.25f * (-0.169f*drA - 0.331f*dgA + 0.5f*dbA),
                        0.25f * (-0.169f*drB - 0.331f*dgB + 0.5f*dbB));
        *(float2*)(V + c*64 + 2*lane) =
            make_float2(0.25f * ( 0.5f*drA - 0.46f*dgA - 0.04f*dbA),
                        0.25f * ( 0.5f*drB - 0.46f*dgB - 0.04f*dbB));
    }
    __syncwarp();

    // ---- horizontal box filter of one row via prefix sum, emit fp16 ----
    // Y rows from registers
    #pragma unroll
    for (int r = 0; r < 2; ++r) {
        float4* Y = r ? yd1 : yd0;
        if (lane < 8) P[lane] = 0.f;
        float carry = 0.f;
        #pragma unroll
        for (int c = 0; c < 4; ++c) {
            float4 v = Y[c];
            float p1 = v.x + v.y, p2 = p1 + v.z, p3 = p2 + v.w;
            float tt = p3;
            #pragma unroll
            for (int off = 1; off < 32; off <<= 1) {
                float o = __shfl_up_sync(FULL, tt, off);
                if (lane >= off) tt += o;
            }
            float bb = tt - p3 + carry;
            ((float4*)(P + 8))[c * 32 + lane] =
                make_float4(bb + v.x, bb + p1, bb + p2, bb + p3);
            carry += __shfl_sync(FULL, tt, 31);
        }
        __syncwarp();
        if (lane < 7) P[8 + WW + lane] = carry;
        __syncwarp();
        __half* dst = g_yh + (long)n * plane + (long)(2*hq + r) * WW;
        #pragma unroll
        for (int c = 0; c < 4; ++c) {
            int x = c * 128 + 4 * lane;
            float4 b = ((const float4*)P)[x >> 2];
            __half2 h01 = __floats2half2_rn(P[x + 15] - b.x, P[x + 16] - b.y);
            __half2 h23 = __floats2half2_rn(P[x + 17] - b.z, P[x + 18] - b.w);
            uint2 st;
            st.x = *(unsigned*)&h01;
            st.y = *(unsigned*)&h23;
            *(uint2*)(dst + x) = st;
        }
        __syncwarp();
    }

    // Chroma rows from smem staging
    #pragma unroll
    for (int r = 0; r < 2; ++r) {
        const float* R = r ? V : U;
        if (lane < 8) P[lane] = 0.f;
        float carry = 0.f;
        #pragma unroll
        for (int c = 0; c < 2; ++c) {
            float4 v = ((const float4*)R)[c * 32 + lane];
            float p1 = v.x + v.y, p2 = p1 + v.z, p3 = p2 + v.w;
            float tt = p3;
            #pragma unroll
            for (int off = 1; off < 32; off <<= 1) {
                float o = __shfl_up_sync(FULL, tt, off);
                if (lane >= off) tt += o;
            }
            float bb = tt - p3 + carry;
            ((float4*)(P + 8))[c * 32 + lane] =
                make_float4(bb + v.x, bb + p1, bb + p2, bb + p3);
            carry += __shfl_sync(FULL, tt, 31);
        }
        __syncwarp();
        if (lane < 7) P[8 + WQ + lane] = carry;
        __syncwarp();
        __half* dst = g_ch + ((long)(r * NB + n) * HQ + hq) * WQ;
        #pragma unroll
        for (int c = 0; c < 2; ++c) {
            int x = c * 128 + 4 * lane;
            float4 b = ((const float4*)P)[x >> 2];
            __half2 h01 = __floats2half2_rn(P[x + 15] - b.x, P[x + 16] - b.y);
            __half2 h23 = __floats2half2_rn(P[x + 17] - b.z, P[x + 18] - b.w);
            uint2 st;
            st.x = *(unsigned*)&h01;
            st.y = *(unsigned*)&h23;
            *(uint2*)(dst + x) = st;
        }
        __syncwarp();
    }
}

// ---------------------------------------------------------------------------
// k_v: vertical 15-tap box (zero-pad SAME) via register sliding window,
// fused square + global reduce + finalize.
// LDG-issue-count optimized: uint4 loads (8 fp16 cols/thread), RGRP=8 rows
// -> same 98K threads / 384 blocks as R9 but HALF the LDG instructions.
// Blocks 0..255: Y. Blocks 256..383: chroma.
// ---------------------------------------------------------------------------
#define NBLK_V 384
#define RGRP 8

__device__ __forceinline__ void ldacc(const __half* p, float* s, float sgn) {
    uint4 u = *(const uint4*)p;
    const __half2* h = (const __half2*)&u;
    #pragma unroll
    for (int j = 0; j < 4; ++j) {
        float2 f = __half22float2(h[j]);
        s[2*j]     += sgn * f.x;
        s[2*j + 1] += sgn * f.y;
    }
}

__global__ void __launch_bounds__(256)
k_v(float* __restrict__ out) {
    __shared__ double red[8];
    const unsigned FULL = 0xFFFFFFFFu;

    int t = blockIdx.x * 256 + threadIdx.x;
    bool isY = t < 65536;

    const __half* src; int H, y0; long stride;
    if (isY) {
        // Y: 64 col-groups of 8, 64 row-groups of 8, 16 images
        int colg = t & 63, rowg = (t >> 6) & 63, n = t >> 12;
        H = HH; stride = WW; y0 = rowg * RGRP;
        src = g_yh + (long)n * HH * WW + 8 * colg;
    } else {
        // chroma: 32 col-groups, 32 row-groups, 32 planes
        int t2 = t - 65536;
        int colg = t2 & 31, rowg = (t2 >> 5) & 31, pl = t2 >> 10;
        H = HQ; stride = WQ; y0 = rowg * RGRP;
        src = g_ch + (long)pl * HQ * WQ + 8 * colg;
    }

    float s[8] = {0.f, 0.f, 0.f, 0.f, 0.f, 0.f, 0.f, 0.f};
    #pragma unroll
    for (int d = -RAD; d <= RAD; ++d) {
        int yy = y0 + d;
        if (yy >= 0 && yy < H)
            ldacc(src + (long)yy * stride, s, 1.f);
    }
    float racc = 0.f;
    #pragma unroll
    for (int i = 0; i < RGRP; ++i) {
        int y = y0 + i;
        racc += s[0]*s[0] + s[1]*s[1] + s[2]*s[2] + s[3]*s[3]
              + s[4]*s[4] + s[5]*s[5] + s[6]*s[6] + s[7]*s[7];
        int ya = y + RAD + 1, yr = y - RAD;
        if (ya < H) ldacc(src + (long)ya * stride, s,  1.f);
        if (yr >= 0) ldacc(src + (long)yr * stride, s, -1.f);
    }
    double dacc = (double)racc;

    #pragma unroll
    for (int off = 16; off > 0; off >>= 1)
        dacc += __shfl_down_sync(FULL, dacc, off);
    int warp = threadIdx.x >> 5, lane = threadIdx.x & 31;
    if (lane == 0) red[warp] = dacc;
    __syncthreads();
    if (threadIdx.x == 0) {
        double sblk = 0.0;
        #pragma unroll
        for (int w = 0; w < 8; ++w) sblk += red[w];
        atomicAdd(&g_acc[isY ? 0 : 1], sblk);
        __threadfence();
        unsigned int prev = atomicAdd(&g_done, 1u);
        if (prev == NBLK_V - 1) {
            volatile double* acc = g_acc;
            double y = acc[0] / (double)((long)NB * HH * WW);
            double c = acc[1] / (double)((long)NB * HQ * WQ);
            out[0] = (float)(y + c);
            g_done = 0u;
        }
    }
}

extern "C" void kernel_launch(void* const* d_in, const int* in_sizes, int n_in,
                              void* d_out, int out_size) {
    const float* in = (const float*)d_in[0];
    const float* tg = (const float*)d_in[1];
    float* out = (float*)d_out;
    (void)in_sizes; (void)n_in; (void)out_size;

    k_diff_h<<<512, 256>>>(in, tg);
    k_v<<<NBLK_V, 256>>>(out);
}